// round 12
// baseline (speedup 1.0000x reference)
#include <cuda_runtime.h>
#include <cuda_bf16.h>
#include <math.h>
#include <stdint.h>

#define N_TOK 8192
#define D 256
#define BM 64
#define BN 64
#define TPB 256    // qk / cvt / mlp
#define WTPB 512   // flash / rbf (16 warps -> 4 per SMSP for latency hiding)
#define KSTR 264   // bf16 stride for [64][256] tiles: 528B rows, ldmatrix conflict-free
#define ESTR 72    // bf16 stride for E tile [64][64]
#define NT (N_TOK / BN)
#define TILE (BM * KSTR)

__device__ __align__(16) __nv_bfloat16 g_q[N_TOK * D];
__device__ __align__(16) __nv_bfloat16 g_k[N_TOK * D];
__device__ __align__(16) __nv_bfloat16 g_x[N_TOK * D];
__device__ __align__(16) __nv_bfloat16 g_attn[N_TOK * D];
__device__ float g_sq[N_TOK];
__device__ float g_feat[N_TOK];

__device__ __forceinline__ uint32_t smem_u32(const void* p) {
    return (uint32_t)__cvta_generic_to_shared(p);
}
__device__ __forceinline__ void ldmx4(uint32_t r[4], uint32_t addr) {
    asm volatile("ldmatrix.sync.aligned.m8n8.x4.shared.b16 {%0,%1,%2,%3}, [%4];"
                 : "=r"(r[0]), "=r"(r[1]), "=r"(r[2]), "=r"(r[3]) : "r"(addr));
}
__device__ __forceinline__ void ldmx4t(uint32_t r[4], uint32_t addr) {
    asm volatile("ldmatrix.sync.aligned.m8n8.x4.trans.shared.b16 {%0,%1,%2,%3}, [%4];"
                 : "=r"(r[0]), "=r"(r[1]), "=r"(r[2]), "=r"(r[3]) : "r"(addr));
}
__device__ __forceinline__ void mma_bf16(float* c, const uint32_t* a, uint32_t b0, uint32_t b1) {
    asm volatile(
        "mma.sync.aligned.m16n8k16.row.col.f32.bf16.bf16.f32 "
        "{%0,%1,%2,%3}, {%4,%5,%6,%7}, {%8,%9}, {%0,%1,%2,%3};"
        : "+f"(c[0]), "+f"(c[1]), "+f"(c[2]), "+f"(c[3])
        : "r"(a[0]), "r"(a[1]), "r"(a[2]), "r"(a[3]), "r"(b0), "r"(b1));
}
__device__ __forceinline__ uint32_t packbf(float x, float y) {
    __nv_bfloat162 p = __float22bfloat162_rn(make_float2(x, y));
    return *reinterpret_cast<uint32_t*>(&p);
}

// ---------------------------------------------------------------------------
// Kernel 0: states fp32 -> bf16 copy
// ---------------------------------------------------------------------------
__global__ void cvt_kernel(const float* __restrict__ x) {
    int i = blockIdx.x * blockDim.x + threadIdx.x;
    float4 t = reinterpret_cast<const float4*>(x)[i];
    uint2 u;
    u.x = packbf(t.x, t.y);
    u.y = packbf(t.z, t.w);
    reinterpret_cast<uint2*>(g_x)[i] = u;
}

// ---------------------------------------------------------------------------
// Kernel 1: q = states @ Wq, k = states @ Wk   (bf16 mma, blockIdx.z selects)
// ---------------------------------------------------------------------------
__global__ void gemm_qk_kernel(const float* __restrict__ x,
                               const float* __restrict__ Wq,
                               const float* __restrict__ Wk) {
    extern __shared__ char smraw[];
    __nv_bfloat16* Xs = (__nv_bfloat16*)smraw;        // [64][KSTR]
    __nv_bfloat16* Wg = Xs + TILE;                    // [64][KSTR]: Wg[n][k] = W[k][ntile+n]

    const float* W = (blockIdx.z == 0) ? Wq : Wk;
    __nv_bfloat16* out = (blockIdx.z == 0) ? g_q : g_k;

    int mtile = blockIdx.y * BM;
    int ntile = blockIdx.x * BN;
    int tid = threadIdx.x, lane = tid & 31, w = tid >> 5;
    int wr = w >> 1, wc = w & 1, gid = lane >> 2, q = lane & 3;

    for (int v = tid; v < BM * (D / 4); v += TPB) {
        int m = v >> 6, c4 = v & 63;
        float4 t = reinterpret_cast<const float4*>(x + (mtile + m) * D)[c4];
        uint2 u;
        u.x = packbf(t.x, t.y);
        u.y = packbf(t.z, t.w);
        *reinterpret_cast<uint2*>(Xs + m * KSTR + c4 * 4) = u;
    }
    for (int v = tid; v < D * (BN / 4); v += TPB) {
        int kk = v >> 4, n4 = (v & 15) * 4;
        float4 t = *reinterpret_cast<const float4*>(W + kk * D + ntile + n4);
        Wg[(n4 + 0) * KSTR + kk] = __float2bfloat16(t.x);
        Wg[(n4 + 1) * KSTR + kk] = __float2bfloat16(t.y);
        Wg[(n4 + 2) * KSTR + kk] = __float2bfloat16(t.z);
        Wg[(n4 + 3) * KSTR + kk] = __float2bfloat16(t.w);
    }
    __syncthreads();

    uint32_t xsa = smem_u32(Xs), wga = smem_u32(Wg);
    uint32_t qa_base = ((16 * wr + (lane & 15)) * KSTR + 8 * (lane >> 4)) * 2;
    uint32_t kb_base = ((32 * wc + (lane & 7) + 8 * (lane >> 4)) * KSTR + 8 * ((lane >> 3) & 1)) * 2;

    float c[4][4] = {};
    #pragma unroll
    for (int ks = 0; ks < 16; ks++) {
        uint32_t a[4], b0[4], b1[4];
        ldmx4(a, xsa + qa_base + ks * 32);
        ldmx4(b0, wga + kb_base + ks * 32);
        ldmx4(b1, wga + kb_base + 16 * KSTR * 2 + ks * 32);
        mma_bf16(c[0], a, b0[0], b0[1]);
        mma_bf16(c[1], a, b0[2], b0[3]);
        mma_bf16(c[2], a, b1[0], b1[1]);
        mma_bf16(c[3], a, b1[2], b1[3]);
    }

    int r0 = mtile + 16 * wr + gid;
    #pragma unroll
    for (int f = 0; f < 4; f++) {
        int col = ntile + 32 * wc + 8 * f + 2 * q;
        *reinterpret_cast<uint32_t*>(out + r0 * D + col)       = packbf(c[f][0], c[f][1]);
        *reinterpret_cast<uint32_t*>(out + (r0 + 8) * D + col) = packbf(c[f][2], c[f][3]);
    }
}

// ---------------------------------------------------------------------------
// Kernel 2: flash attention, 512 threads (16 warps = 4/SMSP).
// Warp (wr,wc), wr=w>>2, wc=w&3.
//   stage1: S rows 16wr x cols 16wc  (A reload per ks; 2 mma/ks)
//   stage2: acc rows 16wr x d-cols 64wc
// Single-buffer smem; tiles staged via register prefetch (R7 scheme).
// ---------------------------------------------------------------------------
__global__ void __launch_bounds__(WTPB, 1) flash_attn_kernel() {
    extern __shared__ char smraw[];
    __nv_bfloat16* Qs = (__nv_bfloat16*)smraw;     // [64][KSTR]
    __nv_bfloat16* Ks = Qs + TILE;                 // [64][KSTR]
    __nv_bfloat16* Xs = Ks + TILE;                 // [64][KSTR]
    __nv_bfloat16* Es = Xs + TILE;                 // [64][ESTR]
    float* red = (float*)(Es + BM * ESTR);         // [4][64]

    int tid = threadIdx.x, lane = tid & 31, w = tid >> 5;
    int wr = w >> 2, wc = w & 3, gid = lane >> 2, q = lane & 3;
    int mtile = blockIdx.x * BM;

    const uint4* gq4 = reinterpret_cast<const uint4*>(g_q);
    const uint4* gk4 = reinterpret_cast<const uint4*>(g_k);
    const uint4* gx4 = reinterpret_cast<const uint4*>(g_x);

    // Stage Q + tile-0 K/X. Each warp-instruction covers ONE row (conflict-free).
    #pragma unroll
    for (int i = 0; i < 4; i++) {
        int idx = tid + i * WTPB;
        int row = idx >> 5, c16 = idx & 31;
        *((uint4*)(Qs + row * KSTR) + c16) = gq4[(mtile + row) * 32 + c16];
        *((uint4*)(Ks + row * KSTR) + c16) = gk4[row * 32 + c16];
        *((uint4*)(Xs + row * KSTR) + c16) = gx4[row * 32 + c16];
    }
    // Prefetch tile 1
    uint4 pfk[4], pfx[4];
    #pragma unroll
    for (int i = 0; i < 4; i++) {
        int idx = tid + i * WTPB;
        int row = idx >> 5, c16 = idx & 31;
        pfk[i] = gk4[(BN + row) * 32 + c16];
        pfx[i] = gx4[(BN + row) * 32 + c16];
    }
    __syncthreads();

    uint32_t qa = smem_u32(Qs) + ((16 * wr + (lane & 15)) * KSTR + 8 * (lane >> 4)) * 2;
    uint32_t kb = smem_u32(Ks) + ((16 * wc + (lane & 7) + 8 * (lane >> 4)) * KSTR + 8 * ((lane >> 3) & 1)) * 2;
    uint32_t ea = smem_u32(Es) + ((16 * wr + (lane & 15)) * ESTR + 8 * (lane >> 4)) * 2;
    uint32_t xb = smem_u32(Xs) + ((lane & 15) * KSTR + 8 * (lane >> 4)) * 2;

    float acc[8][4];
    #pragma unroll
    for (int f = 0; f < 8; f++)
        acc[f][0] = acc[f][1] = acc[f][2] = acc[f][3] = 0.f;
    float den0 = 0.f, den1 = 0.f;

    for (int jt = 0; jt < NT; jt++) {
        if (jt > 0) {
            __syncthreads();   // readers of Ks/Xs/Es (prev iter) done
            #pragma unroll
            for (int i = 0; i < 4; i++) {
                int idx = tid + i * WTPB;
                int row = idx >> 5, c16 = idx & 31;
                *((uint4*)(Ks + row * KSTR) + c16) = pfk[i];
                *((uint4*)(Xs + row * KSTR) + c16) = pfx[i];
            }
            __syncthreads();
        }
        if (jt + 1 < NT) {   // issue next tile's loads under compute shadow
            int jb2 = (jt + 1) * BN;
            #pragma unroll
            for (int i = 0; i < 4; i++) {
                int idx = tid + i * WTPB;
                int row = idx >> 5, c16 = idx & 31;
                pfk[i] = gk4[(jb2 + row) * 32 + c16];
                pfx[i] = gx4[(jb2 + row) * 32 + c16];
            }
        }

        // Stage 1: S = Q @ K^T  (rows 16wr, cols 16wc)
        float cS[2][4] = {};
        #pragma unroll
        for (int ks = 0; ks < 16; ks++) {
            uint32_t a[4], b[4];
            ldmx4(a, qa + ks * 32);
            ldmx4(b, kb + ks * 32);
            mma_bf16(cS[0], a, b[0], b[1]);
            mma_bf16(cS[1], a, b[2], b[3]);
        }
        // E = exp(S/16)
        #pragma unroll
        for (int c = 0; c < 2; c++) {
            float e0 = __expf(cS[c][0] * 0.0625f);
            float e1 = __expf(cS[c][1] * 0.0625f);
            float e2 = __expf(cS[c][2] * 0.0625f);
            float e3 = __expf(cS[c][3] * 0.0625f);
            den0 += e0 + e1; den1 += e2 + e3;
            int col = 16 * wc + 8 * c + 2 * q;
            *reinterpret_cast<uint32_t*>(Es + (16 * wr + gid) * ESTR + col)     = packbf(e0, e1);
            *reinterpret_cast<uint32_t*>(Es + (16 * wr + gid + 8) * ESTR + col) = packbf(e2, e3);
        }
        __syncthreads();

        // Stage 2: acc += E @ X  (rows 16wr, d-cols 64wc)
        #pragma unroll
        for (int ks = 0; ks < 4; ks++) {
            uint32_t a[4];
            ldmx4(a, ea + ks * 32);
            #pragma unroll
            for (int u = 0; u < 4; u++) {
                uint32_t b[4];
                ldmx4t(b, xb + ks * (16 * KSTR * 2) + (64 * wc + 16 * u) * 2);
                mma_bf16(acc[2 * u],     a, b[0], b[1]);
                mma_bf16(acc[2 * u + 1], a, b[2], b[3]);
            }
        }
    }

    // den: quad-reduce then sum 4 wc-groups via smem
    den0 += __shfl_xor_sync(0xffffffffu, den0, 1);
    den0 += __shfl_xor_sync(0xffffffffu, den0, 2);
    den1 += __shfl_xor_sync(0xffffffffu, den1, 1);
    den1 += __shfl_xor_sync(0xffffffffu, den1, 2);
    __syncthreads();
    if (q == 0) {
        red[wc * 64 + 16 * wr + gid]     = den0;
        red[wc * 64 + 16 * wr + gid + 8] = den1;
    }
    __syncthreads();
    int r = 16 * wr + gid;
    float rinv0 = 1.0f / (red[r] + red[64 + r] + red[128 + r] + red[192 + r]);
    float rinv1 = 1.0f / (red[r + 8] + red[64 + r + 8] + red[128 + r + 8] + red[192 + r + 8]);

    float sq0 = 0.f, sq1 = 0.f;
    int r0 = mtile + r;
    #pragma unroll
    for (int f = 0; f < 8; f++) {
        int col = 64 * wc + 8 * f + 2 * q;
        uint32_t p0 = packbf(acc[f][0] * rinv0, acc[f][1] * rinv0);
        uint32_t p1 = packbf(acc[f][2] * rinv1, acc[f][3] * rinv1);
        *reinterpret_cast<uint32_t*>(g_attn + r0 * D + col)       = p0;
        *reinterpret_cast<uint32_t*>(g_attn + (r0 + 8) * D + col) = p1;
        float2 v0 = __bfloat1622float2(*reinterpret_cast<__nv_bfloat162*>(&p0));
        float2 v1 = __bfloat1622float2(*reinterpret_cast<__nv_bfloat162*>(&p1));
        sq0 += v0.x * v0.x + v0.y * v0.y;
        sq1 += v1.x * v1.x + v1.y * v1.y;
    }
    sq0 += __shfl_xor_sync(0xffffffffu, sq0, 1);
    sq0 += __shfl_xor_sync(0xffffffffu, sq0, 2);
    sq1 += __shfl_xor_sync(0xffffffffu, sq1, 1);
    sq1 += __shfl_xor_sync(0xffffffffu, sq1, 2);
    __syncthreads();   // den reads done before red reuse
    if (q == 0) {
        red[wc * 64 + r]     = sq0;
        red[wc * 64 + r + 8] = sq1;
    }
    __syncthreads();
    if (tid < 64)
        g_sq[mtile + tid] = red[tid] + red[64 + tid] + red[128 + tid] + red[192 + tid];
}

// ---------------------------------------------------------------------------
// Kernel 3: RBF stage, 512 threads. Warp (wr,wc): rows 16wr x cols 16wc.
// A fragments (16 rows x K=256) register-resident (64 regs, loaded once);
// B tile + sqj staged via register prefetch (R7 scheme).
// ---------------------------------------------------------------------------
__global__ void __launch_bounds__(WTPB, 1) rbf_feat_kernel() {
    extern __shared__ char smraw[];
    __nv_bfloat16* As = (__nv_bfloat16*)smraw;   // [64][KSTR] resident attn rows
    __nv_bfloat16* Bs = As + TILE;               // [64][KSTR] j-tile
    float* sqj = (float*)(Bs + TILE);            // [64]
    float* red = sqj + 64;                       // [4][64]

    int tid = threadIdx.x, lane = tid & 31, w = tid >> 5;
    int wr = w >> 2, wc = w & 3, gid = lane >> 2, q = lane & 3;
    int mtile = blockIdx.x * BM;

    const uint4* ga4 = reinterpret_cast<const uint4*>(g_attn);
    #pragma unroll
    for (int i = 0; i < 4; i++) {
        int idx = tid + i * WTPB;
        int row = idx >> 5, c16 = idx & 31;
        *((uint4*)(As + row * KSTR) + c16) = ga4[(mtile + row) * 32 + c16];
    }
    // Prefetch tile 0
    uint4 pf[4];
    #pragma unroll
    for (int i = 0; i < 4; i++) {
        int idx = tid + i * WTPB;
        int row = idx >> 5, c16 = idx & 31;
        pf[i] = ga4[row * 32 + c16];
    }
    __syncthreads();

    // A fragments resident: rows 16wr + {0..15}, all K (64 regs)
    uint32_t aa = smem_u32(As) + ((16 * wr + (lane & 15)) * KSTR + 8 * (lane >> 4)) * 2;
    uint32_t afrag[16][4];
    #pragma unroll
    for (int ks = 0; ks < 16; ks++) ldmx4(afrag[ks], aa + ks * 32);

    uint32_t kb = smem_u32(Bs) + ((16 * wc + (lane & 7) + 8 * (lane >> 4)) * KSTR + 8 * ((lane >> 3) & 1)) * 2;

    float sqi0 = g_sq[mtile + 16 * wr + gid];
    float sqi1 = g_sq[mtile + 16 * wr + gid + 8];
    float fs0 = 0.f, fs1 = 0.f;

    for (int jt = 0; jt < NT; jt++) {
        __syncthreads();   // Bs readers done
        #pragma unroll
        for (int i = 0; i < 4; i++) {
            int idx = tid + i * WTPB;
            int row = idx >> 5, c16 = idx & 31;
            *((uint4*)(Bs + row * KSTR) + c16) = pf[i];
        }
        if (tid < 64) sqj[tid] = g_sq[jt * BN + tid];
        __syncthreads();
        if (jt + 1 < NT) {
            int jb2 = (jt + 1) * BN;
            #pragma unroll
            for (int i = 0; i < 4; i++) {
                int idx = tid + i * WTPB;
                int row = idx >> 5, c16 = idx & 31;
                pf[i] = ga4[(jb2 + row) * 32 + c16];
            }
        }

        float cf[2][4] = {};
        #pragma unroll
        for (int ks = 0; ks < 16; ks++) {
            uint32_t b[4];
            ldmx4(b, kb + ks * 32);
            mma_bf16(cf[0], afrag[ks], b[0], b[1]);
            mma_bf16(cf[1], afrag[ks], b[2], b[3]);
        }

        #pragma unroll
        for (int c = 0; c < 2; c++) {
            int col = 16 * wc + 8 * c + 2 * q;
            float sj0 = sqj[col], sj1 = sqj[col + 1];
            fs0 += __expf(-fmaxf(sqi0 + sj0 - 2.0f * cf[c][0], 0.0f));
            fs0 += __expf(-fmaxf(sqi0 + sj1 - 2.0f * cf[c][1], 0.0f));
            fs1 += __expf(-fmaxf(sqi1 + sj0 - 2.0f * cf[c][2], 0.0f));
            fs1 += __expf(-fmaxf(sqi1 + sj1 - 2.0f * cf[c][3], 0.0f));
        }
    }

    fs0 += __shfl_xor_sync(0xffffffffu, fs0, 1);
    fs0 += __shfl_xor_sync(0xffffffffu, fs0, 2);
    fs1 += __shfl_xor_sync(0xffffffffu, fs1, 1);
    fs1 += __shfl_xor_sync(0xffffffffu, fs1, 2);
    __syncthreads();
    if (q == 0) {
        red[wc * 64 + 16 * wr + gid]     = fs0;
        red[wc * 64 + 16 * wr + gid + 8] = fs1;
    }
    __syncthreads();
    if (tid < 64)
        g_feat[mtile + tid] = (red[tid] + red[64 + tid] + red[128 + tid] + red[192 + tid])
                              * (1.0f / (float)N_TOK);
}

// ---------------------------------------------------------------------------
// Kernel 4: MLP head
// ---------------------------------------------------------------------------
__global__ void mlp_kernel(const float* __restrict__ W1, const float* __restrict__ b1,
                           const float* __restrict__ W2, const float* __restrict__ b2,
                           float* __restrict__ out) {
    __shared__ float w1[64], bb1[64], w2[64];
    int tid = threadIdx.x;
    if (tid < 64) { w1[tid] = W1[tid]; bb1[tid] = b1[tid]; w2[tid] = W2[tid]; }
    __syncthreads();
    int i = blockIdx.x * blockDim.x + tid;
    if (i >= N_TOK) return;
    float f = g_feat[i];
    float a = b2[0];
    #pragma unroll
    for (int k2 = 0; k2 < 64; k2++) {
        float h = fmaf(f, w1[k2], bb1[k2]);
        a = fmaf(fmaxf(h, 0.0f), w2[k2], a);
    }
    out[i] = a;
}

// ---------------------------------------------------------------------------
extern "C" void kernel_launch(void* const* d_in, const int* in_sizes, int n_in,
                              void* d_out, int out_size) {
    const float* states = (const float*)d_in[0];
    const float* Wq     = (const float*)d_in[1];
    const float* Wk     = (const float*)d_in[2];
    const float* W1     = (const float*)d_in[3];
    const float* b1     = (const float*)d_in[4];
    const float* W2     = (const float*)d_in[5];
    const float* b2     = (const float*)d_in[6];
    float* out = (float*)d_out;
    (void)in_sizes; (void)n_in; (void)out_size;

    size_t smem_qk    = (size_t)(2 * TILE) * 2;
    size_t smem_flash = (size_t)(3 * TILE + BM * ESTR) * 2 + 256 * 4;
    size_t smem_rbf   = (size_t)(2 * TILE) * 2 + (64 + 256) * 4;

    (void)cudaFuncSetAttribute(gemm_qk_kernel,    cudaFuncAttributeMaxDynamicSharedMemorySize, (int)smem_qk);
    (void)cudaFuncSetAttribute(flash_attn_kernel, cudaFuncAttributeMaxDynamicSharedMemorySize, (int)smem_flash);
    (void)cudaFuncSetAttribute(rbf_feat_kernel,   cudaFuncAttributeMaxDynamicSharedMemorySize, (int)smem_rbf);

    cvt_kernel<<<(N_TOK * D / 4) / TPB, TPB>>>(states);
    dim3 g1(D / BN, N_TOK / BM, 2);
    gemm_qk_kernel<<<g1, TPB, smem_qk>>>(states, Wq, Wk);
    flash_attn_kernel<<<N_TOK / BM, WTPB, smem_flash>>>();
    rbf_feat_kernel<<<N_TOK / BM, WTPB, smem_rbf>>>();
    mlp_kernel<<<N_TOK / TPB, TPB>>>(W1, b1, W2, b2, out);
}

// round 13
// speedup vs baseline: 1.0595x; 1.0595x over previous
#include <cuda_runtime.h>
#include <cuda_bf16.h>
#include <math.h>
#include <stdint.h>

#define N_TOK 8192
#define D 256
#define BM 64
#define BN 64
#define TPB 256
#define KSTR 264   // bf16 stride for [64][256] tiles: 528B rows, ldmatrix conflict-free
#define ESTR 72    // bf16 stride for E tile [64][64]
#define NT (N_TOK / BN)
#define TILE (BM * KSTR)

__device__ __align__(16) __nv_bfloat16 g_q[N_TOK * D];
__device__ __align__(16) __nv_bfloat16 g_k[N_TOK * D];
__device__ __align__(16) __nv_bfloat16 g_x[N_TOK * D];
__device__ __align__(16) __nv_bfloat16 g_attn[N_TOK * D];
__device__ float g_sq[N_TOK];
__device__ float g_feat[N_TOK];

__device__ __forceinline__ uint32_t smem_u32(const void* p) {
    return (uint32_t)__cvta_generic_to_shared(p);
}
__device__ __forceinline__ void ldmx4(uint32_t r[4], uint32_t addr) {
    asm volatile("ldmatrix.sync.aligned.m8n8.x4.shared.b16 {%0,%1,%2,%3}, [%4];"
                 : "=r"(r[0]), "=r"(r[1]), "=r"(r[2]), "=r"(r[3]) : "r"(addr));
}
__device__ __forceinline__ void ldmx4t(uint32_t r[4], uint32_t addr) {
    asm volatile("ldmatrix.sync.aligned.m8n8.x4.trans.shared.b16 {%0,%1,%2,%3}, [%4];"
                 : "=r"(r[0]), "=r"(r[1]), "=r"(r[2]), "=r"(r[3]) : "r"(addr));
}
__device__ __forceinline__ void mma_bf16(float* c, const uint32_t* a, uint32_t b0, uint32_t b1) {
    asm volatile(
        "mma.sync.aligned.m16n8k16.row.col.f32.bf16.bf16.f32 "
        "{%0,%1,%2,%3}, {%4,%5,%6,%7}, {%8,%9}, {%0,%1,%2,%3};"
        : "+f"(c[0]), "+f"(c[1]), "+f"(c[2]), "+f"(c[3])
        : "r"(a[0]), "r"(a[1]), "r"(a[2]), "r"(a[3]), "r"(b0), "r"(b1));
}
__device__ __forceinline__ uint32_t packbf(float x, float y) {
    __nv_bfloat162 p = __float22bfloat162_rn(make_float2(x, y));
    return *reinterpret_cast<uint32_t*>(&p);
}
__device__ __forceinline__ void cp16(uint32_t dst, const void* src) {
    asm volatile("cp.async.cg.shared.global [%0], [%1], 16;" :: "r"(dst), "l"(src));
}
__device__ __forceinline__ void cp_commit() { asm volatile("cp.async.commit_group;"); }
template <int N> __device__ __forceinline__ void cp_wait() {
    asm volatile("cp.async.wait_group %0;" :: "n"(N));
}

// ---------------------------------------------------------------------------
// Kernel 0: states fp32 -> bf16 copy
// ---------------------------------------------------------------------------
__global__ void cvt_kernel(const float* __restrict__ x) {
    int i = blockIdx.x * blockDim.x + threadIdx.x;
    float4 t = reinterpret_cast<const float4*>(x)[i];
    uint2 u;
    u.x = packbf(t.x, t.y);
    u.y = packbf(t.z, t.w);
    reinterpret_cast<uint2*>(g_x)[i] = u;
}

// ---------------------------------------------------------------------------
// Kernel 1: q = states @ Wq, k = states @ Wk   (bf16 mma, blockIdx.z selects)
// ---------------------------------------------------------------------------
__global__ void gemm_qk_kernel(const float* __restrict__ x,
                               const float* __restrict__ Wq,
                               const float* __restrict__ Wk) {
    extern __shared__ char smraw[];
    __nv_bfloat16* Xs = (__nv_bfloat16*)smraw;        // [64][KSTR]
    __nv_bfloat16* Wg = Xs + TILE;                    // [64][KSTR]: Wg[n][k] = W[k][ntile+n]

    const float* W = (blockIdx.z == 0) ? Wq : Wk;
    __nv_bfloat16* out = (blockIdx.z == 0) ? g_q : g_k;

    int mtile = blockIdx.y * BM;
    int ntile = blockIdx.x * BN;
    int tid = threadIdx.x, lane = tid & 31, w = tid >> 5;
    int wr = w >> 1, wc = w & 1, gid = lane >> 2, q = lane & 3;

    for (int v = tid; v < BM * (D / 4); v += TPB) {
        int m = v >> 6, c4 = v & 63;
        float4 t = reinterpret_cast<const float4*>(x + (mtile + m) * D)[c4];
        uint2 u;
        u.x = packbf(t.x, t.y);
        u.y = packbf(t.z, t.w);
        *reinterpret_cast<uint2*>(Xs + m * KSTR + c4 * 4) = u;
    }
    for (int v = tid; v < D * (BN / 4); v += TPB) {
        int kk = v >> 4, n4 = (v & 15) * 4;
        float4 t = *reinterpret_cast<const float4*>(W + kk * D + ntile + n4);
        Wg[(n4 + 0) * KSTR + kk] = __float2bfloat16(t.x);
        Wg[(n4 + 1) * KSTR + kk] = __float2bfloat16(t.y);
        Wg[(n4 + 2) * KSTR + kk] = __float2bfloat16(t.z);
        Wg[(n4 + 3) * KSTR + kk] = __float2bfloat16(t.w);
    }
    __syncthreads();

    uint32_t xsa = smem_u32(Xs), wga = smem_u32(Wg);
    uint32_t qa_base = ((16 * wr + (lane & 15)) * KSTR + 8 * (lane >> 4)) * 2;
    uint32_t kb_base = ((32 * wc + (lane & 7) + 8 * (lane >> 4)) * KSTR + 8 * ((lane >> 3) & 1)) * 2;

    float c[4][4] = {};
    #pragma unroll
    for (int ks = 0; ks < 16; ks++) {
        uint32_t a[4], b0[4], b1[4];
        ldmx4(a, xsa + qa_base + ks * 32);
        ldmx4(b0, wga + kb_base + ks * 32);
        ldmx4(b1, wga + kb_base + 16 * KSTR * 2 + ks * 32);
        mma_bf16(c[0], a, b0[0], b0[1]);
        mma_bf16(c[1], a, b0[2], b0[3]);
        mma_bf16(c[2], a, b1[0], b1[1]);
        mma_bf16(c[3], a, b1[2], b1[3]);
    }

    int r0 = mtile + 16 * wr + gid;
    #pragma unroll
    for (int f = 0; f < 4; f++) {
        int col = ntile + 32 * wc + 8 * f + 2 * q;
        *reinterpret_cast<uint32_t*>(out + r0 * D + col)       = packbf(c[f][0], c[f][1]);
        *reinterpret_cast<uint32_t*>(out + (r0 + 8) * D + col) = packbf(c[f][2], c[f][3]);
    }
}

// ---------------------------------------------------------------------------
// Kernel 2: flash attention. Q fragments register-resident; K/X double-
// buffered via cp.async. Two syncs per iter: cp issue moved AFTER sync B,
// which makes the old top-of-loop sync redundant (all readers of the target
// buffer are past sync B by barrier collectivity).
// ---------------------------------------------------------------------------
__global__ void __launch_bounds__(TPB, 1) flash_attn_kernel() {
    extern __shared__ char smraw[];
    __nv_bfloat16* Qs  = (__nv_bfloat16*)smraw;      // [64][KSTR]
    __nv_bfloat16* Ks0 = Qs + TILE;
    __nv_bfloat16* Ks1 = Ks0 + TILE;
    __nv_bfloat16* Xs0 = Ks1 + TILE;
    __nv_bfloat16* Xs1 = Xs0 + TILE;
    __nv_bfloat16* Es  = Xs1 + TILE;                 // [64][ESTR]
    float* red = (float*)(Es + BM * ESTR);           // [2][64]

    int tid = threadIdx.x, lane = tid & 31, w = tid >> 5;
    int wr = w >> 1, wc = w & 1, gid = lane >> 2, q = lane & 3;
    int mtile = blockIdx.x * BM;

    uint32_t ksa[2] = {smem_u32(Ks0), smem_u32(Ks1)};
    uint32_t xsa[2] = {smem_u32(Xs0), smem_u32(Xs1)};
    uint32_t esa = smem_u32(Es);

    // Stage resident Q tile
    const uint4* gq4 = reinterpret_cast<const uint4*>(g_q);
    #pragma unroll
    for (int i = 0; i < 8; i++) {
        uint4 t = gq4[(mtile + w + 8 * i) * 32 + lane];
        *((uint4*)(Qs + (w + 8 * i) * KSTR) + lane) = t;
    }
    // Prologue: tile-0 K/X via cp.async — FULL coverage (one row per warp-op)
    #pragma unroll
    for (int i = 0; i < 8; i++) {
        int idx = tid + i * TPB;
        int row = idx >> 5, c16 = idx & 31;
        cp16(ksa[0] + (row * KSTR + c16 * 8) * 2, g_k + row * D + c16 * 8);
        cp16(xsa[0] + (row * KSTR + c16 * 8) * 2, g_x + row * D + c16 * 8);
    }
    cp_commit();
    __syncthreads();   // Qs staged

    // Q fragments resident (64 regs)
    uint32_t qa = smem_u32(Qs) + ((16 * wr + (lane & 15)) * KSTR + 8 * (lane >> 4)) * 2;
    uint32_t qfrag[16][4];
    #pragma unroll
    for (int ks = 0; ks < 16; ks++) ldmx4(qfrag[ks], qa + ks * 32);

    uint32_t kb_off = ((32 * wc + (lane & 7) + 8 * (lane >> 4)) * KSTR + 8 * ((lane >> 3) & 1)) * 2;
    uint32_t ea_base = ((16 * wr + (lane & 15)) * ESTR + 8 * (lane >> 4)) * 2;
    uint32_t xb_off = ((lane & 15) * KSTR + 8 * (lane >> 4)) * 2;

    float acc[16][4];
    #pragma unroll
    for (int f = 0; f < 16; f++)
        acc[f][0] = acc[f][1] = acc[f][2] = acc[f][3] = 0.f;
    float den0 = 0.f, den1 = 0.f;

    for (int jt = 0; jt < NT; jt++) {
        int cur = jt & 1;
        cp_wait<0>();      // buf[cur] transfer (committed last iter / prologue) done
        __syncthreads();   // sync B: buf[cur] visible; prior readers of buf[1-cur] done

        if (jt + 1 < NT) { // issue next tile into buf[1-cur]; lands during this compute
            int jb = (jt + 1) * BN;
            #pragma unroll
            for (int i = 0; i < 8; i++) {
                int idx = tid + i * TPB;
                int row = idx >> 5, c16 = idx & 31;
                cp16(ksa[1 - cur] + (row * KSTR + c16 * 8) * 2, g_k + (jb + row) * D + c16 * 8);
                cp16(xsa[1 - cur] + (row * KSTR + c16 * 8) * 2, g_x + (jb + row) * D + c16 * 8);
            }
            cp_commit();
        }

        // Stage 1: S = Q @ K^T on Ks[cur]  (A resident)
        float cS[4][4] = {};
        uint32_t kb = ksa[cur] + kb_off;
        #pragma unroll
        for (int ks = 0; ks < 16; ks++) {
            uint32_t b0[4], b1[4];
            ldmx4(b0, kb + ks * 32);
            ldmx4(b1, kb + 16 * KSTR * 2 + ks * 32);
            mma_bf16(cS[0], qfrag[ks], b0[0], b0[1]);
            mma_bf16(cS[1], qfrag[ks], b0[2], b0[3]);
            mma_bf16(cS[2], qfrag[ks], b1[0], b1[1]);
            mma_bf16(cS[3], qfrag[ks], b1[2], b1[3]);
        }

        // E = exp(S/16)
        #pragma unroll
        for (int f = 0; f < 4; f++) {
            float e0 = __expf(cS[f][0] * 0.0625f);
            float e1 = __expf(cS[f][1] * 0.0625f);
            float e2 = __expf(cS[f][2] * 0.0625f);
            float e3 = __expf(cS[f][3] * 0.0625f);
            den0 += e0 + e1; den1 += e2 + e3;
            int col = 32 * wc + 8 * f + 2 * q;
            *reinterpret_cast<uint32_t*>(Es + (16 * wr + gid) * ESTR + col)     = packbf(e0, e1);
            *reinterpret_cast<uint32_t*>(Es + (16 * wr + gid + 8) * ESTR + col) = packbf(e2, e3);
        }
        __syncthreads();   // sync C: E visible

        // Stage 2: acc += E @ X on Xs[cur]
        #pragma unroll
        for (int ks = 0; ks < 4; ks++) {
            uint32_t a[4];
            ldmx4(a, esa + ea_base + ks * 32);
            #pragma unroll
            for (int u = 0; u < 8; u++) {
                uint32_t b[4];
                ldmx4t(b, xsa[cur] + xb_off + ks * (16 * KSTR * 2) + (128 * wc + 16 * u) * 2);
                mma_bf16(acc[2 * u],     a, b[0], b[1]);
                mma_bf16(acc[2 * u + 1], a, b[2], b[3]);
            }
        }
    }

    // den reduce: quad lanes then cross-wc via smem
    den0 += __shfl_xor_sync(0xffffffffu, den0, 1);
    den0 += __shfl_xor_sync(0xffffffffu, den0, 2);
    den1 += __shfl_xor_sync(0xffffffffu, den1, 1);
    den1 += __shfl_xor_sync(0xffffffffu, den1, 2);
    __syncthreads();
    if (q == 0) {
        red[wc * 64 + 16 * wr + gid]     = den0;
        red[wc * 64 + 16 * wr + gid + 8] = den1;
    }
    __syncthreads();
    float rinv0 = 1.0f / (red[16 * wr + gid]     + red[64 + 16 * wr + gid]);
    float rinv1 = 1.0f / (red[16 * wr + gid + 8] + red[64 + 16 * wr + gid + 8]);

    float sq0 = 0.f, sq1 = 0.f;
    int r0 = mtile + 16 * wr + gid;
    #pragma unroll
    for (int f = 0; f < 16; f++) {
        int col = 128 * wc + 8 * f + 2 * q;
        uint32_t p0 = packbf(acc[f][0] * rinv0, acc[f][1] * rinv0);
        uint32_t p1 = packbf(acc[f][2] * rinv1, acc[f][3] * rinv1);
        *reinterpret_cast<uint32_t*>(g_attn + r0 * D + col)       = p0;
        *reinterpret_cast<uint32_t*>(g_attn + (r0 + 8) * D + col) = p1;
        float2 v0 = __bfloat1622float2(*reinterpret_cast<__nv_bfloat162*>(&p0));
        float2 v1 = __bfloat1622float2(*reinterpret_cast<__nv_bfloat162*>(&p1));
        sq0 += v0.x * v0.x + v0.y * v0.y;
        sq1 += v1.x * v1.x + v1.y * v1.y;
    }
    sq0 += __shfl_xor_sync(0xffffffffu, sq0, 1);
    sq0 += __shfl_xor_sync(0xffffffffu, sq0, 2);
    sq1 += __shfl_xor_sync(0xffffffffu, sq1, 1);
    sq1 += __shfl_xor_sync(0xffffffffu, sq1, 2);
    __syncthreads();   // den reads done before red reuse
    if (q == 0) {
        red[wc * 64 + 16 * wr + gid]     = sq0;
        red[wc * 64 + 16 * wr + gid + 8] = sq1;
    }
    __syncthreads();
    if (tid < 64) g_sq[mtile + tid] = red[tid] + red[64 + tid];
}

// ---------------------------------------------------------------------------
// Kernel 3: RBF stage (R7 base). A fragments register-resident; Bs double-
// buffered with register prefetch -> ONE sync per iter; exp deferred one tile
// so MUFU overlaps the next tile's ldmx/mma chain.
// ---------------------------------------------------------------------------
__global__ void __launch_bounds__(TPB, 1) rbf_feat_kernel() {
    extern __shared__ char smraw[];
    __nv_bfloat16* As  = (__nv_bfloat16*)smraw;   // [64][KSTR] resident attn rows
    __nv_bfloat16* Bs0 = As + TILE;               // [64][KSTR] x2
    __nv_bfloat16* Bs1 = Bs0 + TILE;
    float* red = (float*)(Bs1 + TILE);            // [4][64]

    int tid = threadIdx.x, lane = tid & 31, w = tid >> 5;
    int wr = w >> 2, wc = w & 3, gid = lane >> 2, q = lane & 3;
    int mtile = blockIdx.x * BM;

    uint32_t bsa[2] = {smem_u32(Bs0), smem_u32(Bs1)};

    const uint4* ga4 = reinterpret_cast<const uint4*>(g_attn);
    #pragma unroll
    for (int i = 0; i < 8; i++) {
        uint4 t = ga4[(mtile + w + 8 * i) * 32 + lane];
        *((uint4*)(As + (w + 8 * i) * KSTR) + lane) = t;
    }
    // Prefetch tile 0 into registers
    uint4 pf[8];
    #pragma unroll
    for (int i = 0; i < 8; i++) {
        int idx = tid + i * TPB;
        int row = idx >> 5, c16 = idx & 31;
        pf[i] = ga4[row * 32 + c16];
    }
    __syncthreads();   // As staged

    // A fragments resident: rows 32*wr + {0..31}, all K (128 regs)
    uint32_t aa0 = smem_u32(As) + ((32 * wr + (lane & 15)) * KSTR + 8 * (lane >> 4)) * 2;
    uint32_t afrag[16][2][4];
    #pragma unroll
    for (int ks = 0; ks < 16; ks++) {
        ldmx4(afrag[ks][0], aa0 + ks * 32);
        ldmx4(afrag[ks][1], aa0 + 16 * KSTR * 2 + ks * 32);
    }

    uint32_t kb_off = ((16 * wc + (lane & 7) + 8 * (lane >> 4)) * KSTR + 8 * ((lane >> 3) & 1)) * 2;
    int col0 = 16 * wc + 2 * q;   // exp column base (c adds 8)

    float sqi[2][2], fs[2][2] = {};
    #pragma unroll
    for (int g = 0; g < 2; g++) {
        sqi[g][0] = g_sq[mtile + 32 * wr + 16 * g + gid];
        sqi[g][1] = g_sq[mtile + 32 * wr + 16 * g + gid + 8];
    }

    float cf[2][2][2][4];   // [buf][g][c][4]

    for (int jt = 0; jt < NT; jt++) {
        int cur = jt & 1;
        // STS into Bs[cur]: its last readers (iter jt-2) are past sync(jt-1)
        #pragma unroll
        for (int i = 0; i < 8; i++) {
            int idx = tid + i * TPB;
            int row = idx >> 5, c16 = idx & 31;
            *((uint4*)(Bs0 + (uint32_t)cur * TILE + row * KSTR) + c16) = pf[i];
        }
        __syncthreads();   // the ONE barrier per iteration
        if (jt + 1 < NT) {
            int jb2 = (jt + 1) * BN;
            #pragma unroll
            for (int i = 0; i < 8; i++) {
                int idx = tid + i * TPB;
                int row = idx >> 5, c16 = idx & 31;
                pf[i] = ga4[(jb2 + row) * 32 + c16];
            }
        }

        // mma -> cf[cur]
        #pragma unroll
        for (int g = 0; g < 2; g++)
            #pragma unroll
            for (int c = 0; c < 2; c++)
                cf[cur][g][c][0] = cf[cur][g][c][1] = cf[cur][g][c][2] = cf[cur][g][c][3] = 0.f;
        uint32_t kb = bsa[cur] + kb_off;
        #pragma unroll
        for (int ks = 0; ks < 16; ks++) {
            uint32_t b[4];
            ldmx4(b, kb + ks * 32);
            mma_bf16(cf[cur][0][0], afrag[ks][0], b[0], b[1]);
            mma_bf16(cf[cur][0][1], afrag[ks][0], b[2], b[3]);
            mma_bf16(cf[cur][1][0], afrag[ks][1], b[0], b[1]);
            mma_bf16(cf[cur][1][1], afrag[ks][1], b[2], b[3]);
        }

        // exp for tile jt-1 (registers only) overlaps this tile's mma execution
        if (jt > 0) {
            int pv = 1 - cur;
            const float* sqv = g_sq + (jt - 1) * BN;
            #pragma unroll
            for (int c = 0; c < 2; c++) {
                float sj0 = sqv[col0 + 8 * c], sj1 = sqv[col0 + 8 * c + 1];
                #pragma unroll
                for (int g = 0; g < 2; g++) {
                    fs[g][0] += __expf(-fmaxf(sqi[g][0] + sj0 - 2.0f * cf[pv][g][c][0], 0.0f));
                    fs[g][0] += __expf(-fmaxf(sqi[g][0] + sj1 - 2.0f * cf[pv][g][c][1], 0.0f));
                    fs[g][1] += __expf(-fmaxf(sqi[g][1] + sj0 - 2.0f * cf[pv][g][c][2], 0.0f));
                    fs[g][1] += __expf(-fmaxf(sqi[g][1] + sj1 - 2.0f * cf[pv][g][c][3], 0.0f));
                }
            }
        }
    }
    {   // drain: exp for tile NT-1
        int pv = (NT - 1) & 1;
        const float* sqv = g_sq + (NT - 1) * BN;
        #pragma unroll
        for (int c = 0; c < 2; c++) {
            float sj0 = sqv[col0 + 8 * c], sj1 = sqv[col0 + 8 * c + 1];
            #pragma unroll
            for (int g = 0; g < 2; g++) {
                fs[g][0] += __expf(-fmaxf(sqi[g][0] + sj0 - 2.0f * cf[pv][g][c][0], 0.0f));
                fs[g][0] += __expf(-fmaxf(sqi[g][0] + sj1 - 2.0f * cf[pv][g][c][1], 0.0f));
                fs[g][1] += __expf(-fmaxf(sqi[g][1] + sj0 - 2.0f * cf[pv][g][c][2], 0.0f));
                fs[g][1] += __expf(-fmaxf(sqi[g][1] + sj1 - 2.0f * cf[pv][g][c][3], 0.0f));
            }
        }
    }

    #pragma unroll
    for (int g = 0; g < 2; g++)
        #pragma unroll
        for (int h = 0; h < 2; h++) {
            fs[g][h] += __shfl_xor_sync(0xffffffffu, fs[g][h], 1);
            fs[g][h] += __shfl_xor_sync(0xffffffffu, fs[g][h], 2);
        }
    __syncthreads();
    if (q == 0) {
        #pragma unroll
        for (int g = 0; g < 2; g++) {
            red[wc * 64 + 32 * wr + 16 * g + gid]     = fs[g][0];
            red[wc * 64 + 32 * wr + 16 * g + gid + 8] = fs[g][1];
        }
    }
    __syncthreads();
    if (tid < 64)
        g_feat[mtile + tid] = (red[tid] + red[64 + tid] + red[128 + tid] + red[192 + tid])
                              * (1.0f / (float)N_TOK);
}

// ---------------------------------------------------------------------------
// Kernel 4: MLP head
// ---------------------------------------------------------------------------
__global__ void mlp_kernel(const float* __restrict__ W1, const float* __restrict__ b1,
                           const float* __restrict__ W2, const float* __restrict__ b2,
                           float* __restrict__ out) {
    __shared__ float w1[64], bb1[64], w2[64];
    int tid = threadIdx.x;
    if (tid < 64) { w1[tid] = W1[tid]; bb1[tid] = b1[tid]; w2[tid] = W2[tid]; }
    __syncthreads();
    int i = blockIdx.x * blockDim.x + tid;
    if (i >= N_TOK) return;
    float f = g_feat[i];
    float a = b2[0];
    #pragma unroll
    for (int k2 = 0; k2 < 64; k2++) {
        float h = fmaf(f, w1[k2], bb1[k2]);
        a = fmaf(fmaxf(h, 0.0f), w2[k2], a);
    }
    out[i] = a;
}

// ---------------------------------------------------------------------------
extern "C" void kernel_launch(void* const* d_in, const int* in_sizes, int n_in,
                              void* d_out, int out_size) {
    const float* states = (const float*)d_in[0];
    const float* Wq     = (const float*)d_in[1];
    const float* Wk     = (const float*)d_in[2];
    const float* W1     = (const float*)d_in[3];
    const float* b1     = (const float*)d_in[4];
    const float* W2     = (const float*)d_in[5];
    const float* b2     = (const float*)d_in[6];
    float* out = (float*)d_out;
    (void)in_sizes; (void)n_in; (void)out_size;

    size_t smem_qk    = (size_t)(2 * TILE) * 2;
    size_t smem_flash = (size_t)(5 * TILE + BM * ESTR) * 2 + 512;
    size_t smem_rbf   = (size_t)(3 * TILE) * 2 + 256 * 4;

    (void)cudaFuncSetAttribute(gemm_qk_kernel,    cudaFuncAttributeMaxDynamicSharedMemorySize, (int)smem_qk);
    (void)cudaFuncSetAttribute(flash_attn_kernel, cudaFuncAttributeMaxDynamicSharedMemorySize, (int)smem_flash);
    (void)cudaFuncSetAttribute(rbf_feat_kernel,   cudaFuncAttributeMaxDynamicSharedMemorySize, (int)smem_rbf);

    cvt_kernel<<<(N_TOK * D / 4) / TPB, TPB>>>(states);
    dim3 g1(D / BN, N_TOK / BM, 2);
    gemm_qk_kernel<<<g1, TPB, smem_qk>>>(states, Wq, Wk);
    flash_attn_kernel<<<N_TOK / BM, TPB, smem_flash>>>();
    rbf_feat_kernel<<<N_TOK / BM, TPB, smem_rbf>>>();
    mlp_kernel<<<N_TOK / TPB, TPB>>>(W1, b1, W2, b2, out);
}

// round 15
// speedup vs baseline: 1.1506x; 1.0860x over previous
#include <cuda_runtime.h>
#include <cuda_bf16.h>
#include <math.h>
#include <stdint.h>

#define N_TOK 8192
#define D 256
#define BM 64
#define BN 64
#define TPB 256
#define KSTR 264   // bf16 stride for [64][256] tiles: 528B rows, ldmatrix conflict-free
#define ESTR 72    // bf16 stride for E tile [64][64]
#define NT (N_TOK / BN)
#define TILE (BM * KSTR)

__device__ __align__(16) __nv_bfloat16 g_q[N_TOK * D];
__device__ __align__(16) __nv_bfloat16 g_k[N_TOK * D];
__device__ __align__(16) __nv_bfloat16 g_x[N_TOK * D];
__device__ __align__(16) __nv_bfloat16 g_attn[N_TOK * D];
__device__ float g_sq[N_TOK];
__device__ float g_feat[N_TOK];

__device__ __forceinline__ uint32_t smem_u32(const void* p) {
    return (uint32_t)__cvta_generic_to_shared(p);
}
__device__ __forceinline__ void ldmx4(uint32_t r[4], uint32_t addr) {
    asm volatile("ldmatrix.sync.aligned.m8n8.x4.shared.b16 {%0,%1,%2,%3}, [%4];"
                 : "=r"(r[0]), "=r"(r[1]), "=r"(r[2]), "=r"(r[3]) : "r"(addr));
}
__device__ __forceinline__ void ldmx4t(uint32_t r[4], uint32_t addr) {
    asm volatile("ldmatrix.sync.aligned.m8n8.x4.trans.shared.b16 {%0,%1,%2,%3}, [%4];"
                 : "=r"(r[0]), "=r"(r[1]), "=r"(r[2]), "=r"(r[3]) : "r"(addr));
}
__device__ __forceinline__ void mma_bf16(float* c, const uint32_t* a, uint32_t b0, uint32_t b1) {
    asm volatile(
        "mma.sync.aligned.m16n8k16.row.col.f32.bf16.bf16.f32 "
        "{%0,%1,%2,%3}, {%4,%5,%6,%7}, {%8,%9}, {%0,%1,%2,%3};"
        : "+f"(c[0]), "+f"(c[1]), "+f"(c[2]), "+f"(c[3])
        : "r"(a[0]), "r"(a[1]), "r"(a[2]), "r"(a[3]), "r"(b0), "r"(b1));
}
__device__ __forceinline__ uint32_t packbf(float x, float y) {
    __nv_bfloat162 p = __float22bfloat162_rn(make_float2(x, y));
    return *reinterpret_cast<uint32_t*>(&p);
}
__device__ __forceinline__ void cp16(uint32_t dst, const void* src) {
    asm volatile("cp.async.cg.shared.global [%0], [%1], 16;" :: "r"(dst), "l"(src));
}
__device__ __forceinline__ void cp_commit() { asm volatile("cp.async.commit_group;"); }
template <int N> __device__ __forceinline__ void cp_wait() {
    asm volatile("cp.async.wait_group %0;" :: "n"(N));
}

// ---------------------------------------------------------------------------
// Kernel 0: states fp32 -> bf16 copy
// ---------------------------------------------------------------------------
__global__ void cvt_kernel(const float* __restrict__ x) {
    int i = blockIdx.x * blockDim.x + threadIdx.x;
    float4 t = reinterpret_cast<const float4*>(x)[i];
    uint2 u;
    u.x = packbf(t.x, t.y);
    u.y = packbf(t.z, t.w);
    reinterpret_cast<uint2*>(g_x)[i] = u;
}

// ---------------------------------------------------------------------------
// Kernel 1: q = states @ Wq, k = states @ Wk   (bf16 mma, blockIdx.z selects)
// ---------------------------------------------------------------------------
__global__ void gemm_qk_kernel(const float* __restrict__ x,
                               const float* __restrict__ Wq,
                               const float* __restrict__ Wk) {
    extern __shared__ char smraw[];
    __nv_bfloat16* Xs = (__nv_bfloat16*)smraw;        // [64][KSTR]
    __nv_bfloat16* Wg = Xs + TILE;                    // [64][KSTR]: Wg[n][k] = W[k][ntile+n]

    const float* W = (blockIdx.z == 0) ? Wq : Wk;
    __nv_bfloat16* out = (blockIdx.z == 0) ? g_q : g_k;

    int mtile = blockIdx.y * BM;
    int ntile = blockIdx.x * BN;
    int tid = threadIdx.x, lane = tid & 31, w = tid >> 5;
    int wr = w >> 1, wc = w & 1, gid = lane >> 2, q = lane & 3;

    for (int v = tid; v < BM * (D / 4); v += TPB) {
        int m = v >> 6, c4 = v & 63;
        float4 t = reinterpret_cast<const float4*>(x + (mtile + m) * D)[c4];
        uint2 u;
        u.x = packbf(t.x, t.y);
        u.y = packbf(t.z, t.w);
        *reinterpret_cast<uint2*>(Xs + m * KSTR + c4 * 4) = u;
    }
    for (int v = tid; v < D * (BN / 4); v += TPB) {
        int kk = v >> 4, n4 = (v & 15) * 4;
        float4 t = *reinterpret_cast<const float4*>(W + kk * D + ntile + n4);
        Wg[(n4 + 0) * KSTR + kk] = __float2bfloat16(t.x);
        Wg[(n4 + 1) * KSTR + kk] = __float2bfloat16(t.y);
        Wg[(n4 + 2) * KSTR + kk] = __float2bfloat16(t.z);
        Wg[(n4 + 3) * KSTR + kk] = __float2bfloat16(t.w);
    }
    __syncthreads();

    uint32_t xsa = smem_u32(Xs), wga = smem_u32(Wg);
    uint32_t qa_base = ((16 * wr + (lane & 15)) * KSTR + 8 * (lane >> 4)) * 2;
    uint32_t kb_base = ((32 * wc + (lane & 7) + 8 * (lane >> 4)) * KSTR + 8 * ((lane >> 3) & 1)) * 2;

    float c[4][4] = {};
    #pragma unroll
    for (int ks = 0; ks < 16; ks++) {
        uint32_t a[4], b0[4], b1[4];
        ldmx4(a, xsa + qa_base + ks * 32);
        ldmx4(b0, wga + kb_base + ks * 32);
        ldmx4(b1, wga + kb_base + 16 * KSTR * 2 + ks * 32);
        mma_bf16(c[0], a, b0[0], b0[1]);
        mma_bf16(c[1], a, b0[2], b0[3]);
        mma_bf16(c[2], a, b1[0], b1[1]);
        mma_bf16(c[3], a, b1[2], b1[3]);
    }

    int r0 = mtile + 16 * wr + gid;
    #pragma unroll
    for (int f = 0; f < 4; f++) {
        int col = ntile + 32 * wc + 8 * f + 2 * q;
        *reinterpret_cast<uint32_t*>(out + r0 * D + col)       = packbf(c[f][0], c[f][1]);
        *reinterpret_cast<uint32_t*>(out + (r0 + 8) * D + col) = packbf(c[f][2], c[f][3]);
    }
}

// ---------------------------------------------------------------------------
// Kernel 2: flash attention (R13 variant — best measured). Q fragments
// register-resident; K/X double-buffered via cp.async; two syncs per iter
// (cp issue placed AFTER sync B makes a third barrier redundant).
// ---------------------------------------------------------------------------
__global__ void __launch_bounds__(TPB, 1) flash_attn_kernel() {
    extern __shared__ char smraw[];
    __nv_bfloat16* Qs  = (__nv_bfloat16*)smraw;      // [64][KSTR]
    __nv_bfloat16* Ks0 = Qs + TILE;
    __nv_bfloat16* Ks1 = Ks0 + TILE;
    __nv_bfloat16* Xs0 = Ks1 + TILE;
    __nv_bfloat16* Xs1 = Xs0 + TILE;
    __nv_bfloat16* Es  = Xs1 + TILE;                 // [64][ESTR]
    float* red = (float*)(Es + BM * ESTR);           // [2][64]

    int tid = threadIdx.x, lane = tid & 31, w = tid >> 5;
    int wr = w >> 1, wc = w & 1, gid = lane >> 2, q = lane & 3;
    int mtile = blockIdx.x * BM;

    uint32_t ksa[2] = {smem_u32(Ks0), smem_u32(Ks1)};
    uint32_t xsa[2] = {smem_u32(Xs0), smem_u32(Xs1)};
    uint32_t esa = smem_u32(Es);

    // Stage resident Q tile
    const uint4* gq4 = reinterpret_cast<const uint4*>(g_q);
    #pragma unroll
    for (int i = 0; i < 8; i++) {
        uint4 t = gq4[(mtile + w + 8 * i) * 32 + lane];
        *((uint4*)(Qs + (w + 8 * i) * KSTR) + lane) = t;
    }
    // Prologue: tile-0 K/X via cp.async — full coverage (one row per warp-op)
    #pragma unroll
    for (int i = 0; i < 8; i++) {
        int idx = tid + i * TPB;
        int row = idx >> 5, c16 = idx & 31;
        cp16(ksa[0] + (row * KSTR + c16 * 8) * 2, g_k + row * D + c16 * 8);
        cp16(xsa[0] + (row * KSTR + c16 * 8) * 2, g_x + row * D + c16 * 8);
    }
    cp_commit();
    __syncthreads();   // Qs staged

    // Q fragments resident (64 regs)
    uint32_t qa = smem_u32(Qs) + ((16 * wr + (lane & 15)) * KSTR + 8 * (lane >> 4)) * 2;
    uint32_t qfrag[16][4];
    #pragma unroll
    for (int ks = 0; ks < 16; ks++) ldmx4(qfrag[ks], qa + ks * 32);

    uint32_t kb_off = ((32 * wc + (lane & 7) + 8 * (lane >> 4)) * KSTR + 8 * ((lane >> 3) & 1)) * 2;
    uint32_t ea_base = ((16 * wr + (lane & 15)) * ESTR + 8 * (lane >> 4)) * 2;
    uint32_t xb_off = ((lane & 15) * KSTR + 8 * (lane >> 4)) * 2;

    float acc[16][4];
    #pragma unroll
    for (int f = 0; f < 16; f++)
        acc[f][0] = acc[f][1] = acc[f][2] = acc[f][3] = 0.f;
    float den0 = 0.f, den1 = 0.f;

    for (int jt = 0; jt < NT; jt++) {
        int cur = jt & 1;
        cp_wait<0>();      // buf[cur] transfer done
        __syncthreads();   // sync B: buf[cur] visible; prior readers of buf[1-cur] done

        if (jt + 1 < NT) { // issue next tile into buf[1-cur]; lands during compute
            int jb = (jt + 1) * BN;
            #pragma unroll
            for (int i = 0; i < 8; i++) {
                int idx = tid + i * TPB;
                int row = idx >> 5, c16 = idx & 31;
                cp16(ksa[1 - cur] + (row * KSTR + c16 * 8) * 2, g_k + (jb + row) * D + c16 * 8);
                cp16(xsa[1 - cur] + (row * KSTR + c16 * 8) * 2, g_x + (jb + row) * D + c16 * 8);
            }
            cp_commit();
        }

        // Stage 1: S = Q @ K^T on Ks[cur]  (A resident)
        float cS[4][4] = {};
        uint32_t kb = ksa[cur] + kb_off;
        #pragma unroll
        for (int ks = 0; ks < 16; ks++) {
            uint32_t b0[4], b1[4];
            ldmx4(b0, kb + ks * 32);
            ldmx4(b1, kb + 16 * KSTR * 2 + ks * 32);
            mma_bf16(cS[0], qfrag[ks], b0[0], b0[1]);
            mma_bf16(cS[1], qfrag[ks], b0[2], b0[3]);
            mma_bf16(cS[2], qfrag[ks], b1[0], b1[1]);
            mma_bf16(cS[3], qfrag[ks], b1[2], b1[3]);
        }

        // E = exp(S/16)
        #pragma unroll
        for (int f = 0; f < 4; f++) {
            float e0 = __expf(cS[f][0] * 0.0625f);
            float e1 = __expf(cS[f][1] * 0.0625f);
            float e2 = __expf(cS[f][2] * 0.0625f);
            float e3 = __expf(cS[f][3] * 0.0625f);
            den0 += e0 + e1; den1 += e2 + e3;
            int col = 32 * wc + 8 * f + 2 * q;
            *reinterpret_cast<uint32_t*>(Es + (16 * wr + gid) * ESTR + col)     = packbf(e0, e1);
            *reinterpret_cast<uint32_t*>(Es + (16 * wr + gid + 8) * ESTR + col) = packbf(e2, e3);
        }
        __syncthreads();   // sync C: E visible

        // Stage 2: acc += E @ X on Xs[cur]
        #pragma unroll
        for (int ks = 0; ks < 4; ks++) {
            uint32_t a[4];
            ldmx4(a, esa + ea_base + ks * 32);
            #pragma unroll
            for (int u = 0; u < 8; u++) {
                uint32_t b[4];
                ldmx4t(b, xsa[cur] + xb_off + ks * (16 * KSTR * 2) + (128 * wc + 16 * u) * 2);
                mma_bf16(acc[2 * u],     a, b[0], b[1]);
                mma_bf16(acc[2 * u + 1], a, b[2], b[3]);
            }
        }
    }

    // den reduce: quad lanes then cross-wc via smem
    den0 += __shfl_xor_sync(0xffffffffu, den0, 1);
    den0 += __shfl_xor_sync(0xffffffffu, den0, 2);
    den1 += __shfl_xor_sync(0xffffffffu, den1, 1);
    den1 += __shfl_xor_sync(0xffffffffu, den1, 2);
    __syncthreads();
    if (q == 0) {
        red[wc * 64 + 16 * wr + gid]     = den0;
        red[wc * 64 + 16 * wr + gid + 8] = den1;
    }
    __syncthreads();
    float rinv0 = 1.0f / (red[16 * wr + gid]     + red[64 + 16 * wr + gid]);
    float rinv1 = 1.0f / (red[16 * wr + gid + 8] + red[64 + 16 * wr + gid + 8]);

    float sq0 = 0.f, sq1 = 0.f;
    int r0 = mtile + 16 * wr + gid;
    #pragma unroll
    for (int f = 0; f < 16; f++) {
        int col = 128 * wc + 8 * f + 2 * q;
        uint32_t p0 = packbf(acc[f][0] * rinv0, acc[f][1] * rinv0);
        uint32_t p1 = packbf(acc[f][2] * rinv1, acc[f][3] * rinv1);
        *reinterpret_cast<uint32_t*>(g_attn + r0 * D + col)       = p0;
        *reinterpret_cast<uint32_t*>(g_attn + (r0 + 8) * D + col) = p1;
        float2 v0 = __bfloat1622float2(*reinterpret_cast<__nv_bfloat162*>(&p0));
        float2 v1 = __bfloat1622float2(*reinterpret_cast<__nv_bfloat162*>(&p1));
        sq0 += v0.x * v0.x + v0.y * v0.y;
        sq1 += v1.x * v1.x + v1.y * v1.y;
    }
    sq0 += __shfl_xor_sync(0xffffffffu, sq0, 1);
    sq0 += __shfl_xor_sync(0xffffffffu, sq0, 2);
    sq1 += __shfl_xor_sync(0xffffffffu, sq1, 1);
    sq1 += __shfl_xor_sync(0xffffffffu, sq1, 2);
    __syncthreads();   // den reads done before red reuse
    if (q == 0) {
        red[wc * 64 + 16 * wr + gid]     = sq0;
        red[wc * 64 + 16 * wr + gid + 8] = sq1;
    }
    __syncthreads();
    if (tid < 64) g_sq[mtile + tid] = red[tid] + red[64 + tid];
}

// ---------------------------------------------------------------------------
// Kernel 3: RBF stage — exact R7 structure (best measured: 144.9 us, 212 regs).
// A fragments register-resident (128 regs); B tile via register prefetch +
// STS; sqj in smem; immediate exp; 2 syncs per iteration.
// ---------------------------------------------------------------------------
__global__ void __launch_bounds__(TPB, 1) rbf_feat_kernel() {
    extern __shared__ char smraw[];
    __nv_bfloat16* As = (__nv_bfloat16*)smraw;   // [64][KSTR] resident attn rows
    __nv_bfloat16* Bs = As + TILE;               // [64][KSTR] j-tile
    float* sqj = (float*)(Bs + TILE);            // [64]
    float* red = sqj + 64;                       // [4][64]

    int tid = threadIdx.x, lane = tid & 31, w = tid >> 5;
    int wr = w >> 2, wc = w & 3, gid = lane >> 2, q = lane & 3;
    int mtile = blockIdx.x * BM;

    const uint4* ga4 = reinterpret_cast<const uint4*>(g_attn);
    #pragma unroll
    for (int i = 0; i < 8; i++) {
        uint4 t = ga4[(mtile + w + 8 * i) * 32 + lane];
        *((uint4*)(As + (w + 8 * i) * KSTR) + lane) = t;
    }
    __syncthreads();

    // A fragments resident: rows 32*wr + {0..31}, all K (128 regs)
    uint32_t aa0 = smem_u32(As) + ((32 * wr + (lane & 15)) * KSTR + 8 * (lane >> 4)) * 2;
    uint32_t afrag[16][2][4];
    #pragma unroll
    for (int ks = 0; ks < 16; ks++) {
        ldmx4(afrag[ks][0], aa0 + ks * 32);
        ldmx4(afrag[ks][1], aa0 + 16 * KSTR * 2 + ks * 32);
    }

    uint32_t kb = smem_u32(Bs) +
        ((16 * wc + (lane & 7) + 8 * (lane >> 4)) * KSTR + 8 * ((lane >> 3) & 1)) * 2;

    float sqi[2][2], fs[2][2] = {};
    #pragma unroll
    for (int g = 0; g < 2; g++) {
        sqi[g][0] = g_sq[mtile + 32 * wr + 16 * g + gid];
        sqi[g][1] = g_sq[mtile + 32 * wr + 16 * g + gid + 8];
    }

    uint4 pf[8];
    #pragma unroll
    for (int i = 0; i < 8; i++) pf[i] = ga4[(w + 8 * i) * 32 + lane];

    for (int jt = 0; jt < NT; jt++) {
        __syncthreads();
        #pragma unroll
        for (int i = 0; i < 8; i++)
            *((uint4*)(Bs + (w + 8 * i) * KSTR) + lane) = pf[i];
        if (tid < 64) sqj[tid] = g_sq[jt * BN + tid];
        __syncthreads();
        if (jt + 1 < NT) {
            int jb2 = (jt + 1) * BN;
            #pragma unroll
            for (int i = 0; i < 8; i++) pf[i] = ga4[(jb2 + w + 8 * i) * 32 + lane];
        }

        float cf[2][2][4] = {};
        #pragma unroll
        for (int ks = 0; ks < 16; ks++) {
            uint32_t b[4];
            ldmx4(b, kb + ks * 32);
            mma_bf16(cf[0][0], afrag[ks][0], b[0], b[1]);
            mma_bf16(cf[0][1], afrag[ks][0], b[2], b[3]);
            mma_bf16(cf[1][0], afrag[ks][1], b[0], b[1]);
            mma_bf16(cf[1][1], afrag[ks][1], b[2], b[3]);
        }

        #pragma unroll
        for (int g = 0; g < 2; g++) {
            #pragma unroll
            for (int c = 0; c < 2; c++) {
                int col = 16 * wc + 8 * c + 2 * q;
                float sj0 = sqj[col], sj1 = sqj[col + 1];
                fs[g][0] += __expf(-fmaxf(sqi[g][0] + sj0 - 2.0f * cf[g][c][0], 0.0f));
                fs[g][0] += __expf(-fmaxf(sqi[g][0] + sj1 - 2.0f * cf[g][c][1], 0.0f));
                fs[g][1] += __expf(-fmaxf(sqi[g][1] + sj0 - 2.0f * cf[g][c][2], 0.0f));
                fs[g][1] += __expf(-fmaxf(sqi[g][1] + sj1 - 2.0f * cf[g][c][3], 0.0f));
            }
        }
    }

    #pragma unroll
    for (int g = 0; g < 2; g++) {
        #pragma unroll
        for (int h = 0; h < 2; h++) {
            fs[g][h] += __shfl_xor_sync(0xffffffffu, fs[g][h], 1);
            fs[g][h] += __shfl_xor_sync(0xffffffffu, fs[g][h], 2);
        }
    }
    __syncthreads();
    if (q == 0) {
        #pragma unroll
        for (int g = 0; g < 2; g++) {
            red[wc * 64 + 32 * wr + 16 * g + gid]     = fs[g][0];
            red[wc * 64 + 32 * wr + 16 * g + gid + 8] = fs[g][1];
        }
    }
    __syncthreads();
    if (tid < 64)
        g_feat[mtile + tid] = (red[tid] + red[64 + tid] + red[128 + tid] + red[192 + tid])
                              * (1.0f / (float)N_TOK);
}

// ---------------------------------------------------------------------------
// Kernel 4: MLP head
// ---------------------------------------------------------------------------
__global__ void mlp_kernel(const float* __restrict__ W1, const float* __restrict__ b1,
                           const float* __restrict__ W2, const float* __restrict__ b2,
                           float* __restrict__ out) {
    __shared__ float w1[64], bb1[64], w2[64];
    int tid = threadIdx.x;
    if (tid < 64) { w1[tid] = W1[tid]; bb1[tid] = b1[tid]; w2[tid] = W2[tid]; }
    __syncthreads();
    int i = blockIdx.x * blockDim.x + tid;
    if (i >= N_TOK) return;
    float f = g_feat[i];
    float a = b2[0];
    #pragma unroll
    for (int k2 = 0; k2 < 64; k2++) {
        float h = fmaf(f, w1[k2], bb1[k2]);
        a = fmaf(fmaxf(h, 0.0f), w2[k2], a);
    }
    out[i] = a;
}

// ---------------------------------------------------------------------------
extern "C" void kernel_launch(void* const* d_in, const int* in_sizes, int n_in,
                              void* d_out, int out_size) {
    const float* states = (const float*)d_in[0];
    const float* Wq     = (const float*)d_in[1];
    const float* Wk     = (const float*)d_in[2];
    const float* W1     = (const float*)d_in[3];
    const float* b1     = (const float*)d_in[4];
    const float* W2     = (const float*)d_in[5];
    const float* b2     = (const float*)d_in[6];
    float* out = (float*)d_out;
    (void)in_sizes; (void)n_in; (void)out_size;

    size_t smem_qk    = (size_t)(2 * TILE) * 2;
    size_t smem_flash = (size_t)(5 * TILE + BM * ESTR) * 2 + 512;
    size_t smem_rbf   = (size_t)(2 * TILE) * 2 + (64 + 256) * 4;

    (void)cudaFuncSetAttribute(gemm_qk_kernel,    cudaFuncAttributeMaxDynamicSharedMemorySize, (int)smem_qk);
    (void)cudaFuncSetAttribute(flash_attn_kernel, cudaFuncAttributeMaxDynamicSharedMemorySize, (int)smem_flash);
    (void)cudaFuncSetAttribute(rbf_feat_kernel,   cudaFuncAttributeMaxDynamicSharedMemorySize, (int)smem_rbf);

    cvt_kernel<<<(N_TOK * D / 4) / TPB, TPB>>>(states);
    dim3 g1(D / BN, N_TOK / BM, 2);
    gemm_qk_kernel<<<g1, TPB, smem_qk>>>(states, Wq, Wk);
    flash_attn_kernel<<<N_TOK / BM, TPB, smem_flash>>>();
    rbf_feat_kernel<<<N_TOK / BM, TPB, smem_rbf>>>();
    mlp_kernel<<<N_TOK / TPB, TPB>>>(W1, b1, W2, b2, out);
}